// round 11
// baseline (speedup 1.0000x reference)
#include <cuda_runtime.h>
#include <cstdint>

// FWHT, 4096 rows x 16384 fp32. Persistent CTAs (grid=148, 1/SM), 1024 thr.
// Streaming design: cp.async (LDGSTS.128) copies the NEXT row gmem->smem
// (double-buffered) while the current row is computed -> zero-register
// prefetch. All butterfly phases read/write smem in place:
//   P1': regs H16 over bits {13..10} (scalar LDS stride 1024 -> phys 1152)
//   P2': regs H16 over bits {9..6}   (scalar LDS stride 64   -> phys 72)
//   P3': LDS.128 x4 (16 consecutive floats) -> shfl bits {5,4} (lane bits
//        1,0; masks 2,1) -> H16 over bits {3..0} -> scale -> STG.128 x4.
// Swizzle phys(i) = i + 4*(i>>5): injective, 16B-aligned; conflict-free for
// LDGSTS.128 writes, both scalar read/wb patterns, and P3' LDS.128 reads
// (8-lane bank starts {0,16,4,20,8,24,12,28} tile all 32 banks).
// 3 __syncthreads()/row.

#define N_ELEM 16384
#define THREADS 1024
#define BUF_FLOATS 18432   // max phys idx: 1147 + 15*1152 = 18427
#define GRID 148

__device__ __forceinline__ int physz(int i) { return i + ((i >> 5) << 2); }

template <int N>
__device__ __forceinline__ void hadN(float* v) {
#pragma unroll
    for (int s = 1; s < N; s <<= 1) {
#pragma unroll
        for (int i = 0; i < N; i++) {
            if ((i & s) == 0) {
                float a = v[i];
                float b = v[i | s];
                v[i]     = a + b;
                v[i | s] = a - b;
            }
        }
    }
}

// Copy one row (16KB per 1024 threads -> 4x16B per thread) gmem->smem async.
__device__ __forceinline__ void issue_row_copy(float* buf, const float* src,
                                               int t) {
#pragma unroll
    for (int j = 0; j < 4; j++) {
        const int i = (j << 12) + (t << 2);           // logical float index
        uint32_t dst = (uint32_t)__cvta_generic_to_shared(&buf[physz(i)]);
        asm volatile("cp.async.cg.shared.global [%0], [%1], 16;"
                     :: "r"(dst), "l"((const void*)(src + i)) : "memory");
    }
    asm volatile("cp.async.commit_group;" ::: "memory");
}

__global__ __launch_bounds__(THREADS, 1)
void fwht_kernel(const float* __restrict__ in, float* __restrict__ out,
                 int nrows) {
    extern __shared__ float sh[];
    const int t = threadIdx.x;
    const int l = t & 31;

    // Immediate-foldable bases:
    // P1': phys(r<<10 | t)  = p1 + r*1152   (1024 + 4*(1024/32) = 1152)
    const int p1 = t + ((t >> 5) << 2);
    // P2': phys((t>>6)<<10 | r<<6 | (t&63)) = p2 + r*72  (64 + 4*2)
    const int p2 = physz(((t >> 6) << 10) | (t & 63));
    // P3': phys(t<<4) = (t<<4) + 4*(t>>1); +4 per float4 (same 32-seg)
    const int p3 = (t << 4) + ((t >> 1) << 2);

    const float s5 = (l & 2) ? -1.0f : 1.0f;  // bit 5 = lane bit 1
    const float s4 = (l & 1) ? -1.0f : 1.0f;  // bit 4 = lane bit 0

    int row = blockIdx.x;
    int p = 0;
    issue_row_copy(sh, in + (size_t)row * N_ELEM, t);  // row -> buf0

    while (row < nrows) {
        const int nextrow = row + GRID;
        float* __restrict__ buf = sh + p * BUF_FLOATS;
        float* __restrict__ obuf = sh + (p ^ 1) * BUF_FLOATS;

        // B0: this row's copy complete; other buffer's reads (prev P3') done.
        asm volatile("cp.async.wait_group 0;" ::: "memory");
        __syncthreads();
        if (nextrow < nrows)
            issue_row_copy(obuf, in + (size_t)nextrow * N_ELEM, t);

        float v[16];

        // ---- P1': bits {13..10}, stride-1024 scalar, in-place writeback
#pragma unroll
        for (int r = 0; r < 16; r++) v[r] = buf[p1 + r * 1152];
        hadN<16>(v);
#pragma unroll
        for (int r = 0; r < 16; r++) buf[p1 + r * 1152] = v[r];
        __syncthreads();  // B1

        // ---- P2': bits {9..6}, stride-64 scalar, in-place writeback
#pragma unroll
        for (int r = 0; r < 16; r++) v[r] = buf[p2 + r * 72];
        hadN<16>(v);
#pragma unroll
        for (int r = 0; r < 16; r++) buf[p2 + r * 72] = v[r];
        __syncthreads();  // B2

        // ---- P3': 16 consecutive floats via LDS.128 x4
#pragma unroll
        for (int k = 0; k < 4; k++) {
            float4 f = *reinterpret_cast<const float4*>(&buf[p3 + 4 * k]);
            v[4 * k + 0] = f.x; v[4 * k + 1] = f.y;
            v[4 * k + 2] = f.z; v[4 * k + 3] = f.w;
        }

        // bits {5,4} via shfl-xor (lane bits 1,0)
#pragma unroll
        for (int r = 0; r < 16; r++) {
            float q = __shfl_xor_sync(0xffffffffu, v[r], 2);
            v[r] = fmaf(s5, v[r], q);
        }
#pragma unroll
        for (int r = 0; r < 16; r++) {
            float q = __shfl_xor_sync(0xffffffffu, v[r], 1);
            v[r] = fmaf(s4, v[r], q);
        }

        // bits {3..0} in regs
        hadN<16>(v);

        // ---- scale 2^-7, STG.128 x4 (warp writes 2KB contiguous)
        float* __restrict__ pout = out + (size_t)row * N_ELEM + (t << 4);
#pragma unroll
        for (int k = 0; k < 4; k++) {
            float4 f;
            f.x = v[4 * k + 0] * 0.0078125f;
            f.y = v[4 * k + 1] * 0.0078125f;
            f.z = v[4 * k + 2] * 0.0078125f;
            f.w = v[4 * k + 3] * 0.0078125f;
            *reinterpret_cast<float4*>(&pout[4 * k]) = f;
        }

        row = nextrow;
        p ^= 1;
    }
}

extern "C" void kernel_launch(void* const* d_in, const int* in_sizes, int n_in,
                              void* d_out, int out_size) {
    const float* phi = (const float*)d_in[0];
    float* out = (float*)d_out;

    const size_t smem = 2 * BUF_FLOATS * sizeof(float);  // 147456 B
    cudaFuncSetAttribute(fwht_kernel,
                         cudaFuncAttributeMaxDynamicSharedMemorySize,
                         (int)smem);

    const int nrows = in_sizes[0] / N_ELEM;  // 4096
    const int grid = nrows < GRID ? nrows : GRID;
    fwht_kernel<<<grid, THREADS, smem>>>(phi, out, nrows);
}

// round 12
// speedup vs baseline: 1.4752x; 1.4752x over previous
#include <cuda_runtime.h>

// FWHT, 4096 rows x 16384 fp32. Persistent CTAs (grid=148, 1/SM), 1024 thr,
// register prefetch of next row + L2 prefetch (prefetch.global.L2) of row+2.
// Per-row dataflow (R6, best measured):
//   P1: regs H16 over bits {13,12,1,0}  (float4 LDG; vector lanes = bits 1,0)
//   X1 -> P2: regs H16 over bits {11..8}  (same-address writeback)
//   X2 -> P3: regs H16 over bits {7..4}
//   shfl stages over bits {3,2}; scale 2^-7; coalesced STG.
// Swizzle phys(i) = i + 16*(i>>8): injective, 16B-aligned, conflict-free for
// all four smem patterns (verified R5-R9).

#define N_ELEM 16384
#define THREADS 1024
#define SMEM_FLOATS 17408  // max phys index 16383 + 16*63 = 17391
#define GRID 148

__device__ __forceinline__ int physz(int i) { return i + ((i >> 8) << 4); }

template <int N>
__device__ __forceinline__ void hadN(float* v) {
#pragma unroll
    for (int s = 1; s < N; s <<= 1) {
#pragma unroll
        for (int i = 0; i < N; i++) {
            if ((i & s) == 0) {
                float a = v[i];
                float b = v[i | s];
                v[i]     = a + b;
                v[i | s] = a - b;
            }
        }
    }
}

__global__ __launch_bounds__(THREADS, 1)
void fwht_kernel(const float* __restrict__ in, float* __restrict__ out,
                 int nrows) {
    extern __shared__ float sh[];
    const int t = threadIdx.x;
    const int l = t & 31;

    // Immediate-foldable bases:
    // P1: phys(j<<12 | t<<2)                = pa  + j*4352
    // P2: phys((t>>8)<<12 | r<<8 | (t&255)) = pb1 + r*272
    // P3: phys((t>>4)<<8  | r<<4 | (t&15))  = pb2 + r*16
    const int pa  = (t << 2) + ((t >> 6) << 4);
    const int pb1 = physz(((t >> 8) << 12) | (t & 255));
    const int b2  = ((t >> 4) << 8) | (t & 15);
    const int pb2 = physz(b2);

    const float s3 = (l & 8) ? -1.0f : 1.0f;
    const float s2 = (l & 4) ? -1.0f : 1.0f;

    float v[16];

    int row = blockIdx.x;
    {
        const float4* __restrict__ p4 =
            reinterpret_cast<const float4*>(in + (size_t)row * N_ELEM + (t << 2));
#pragma unroll
        for (int j = 0; j < 4; j++) {
            float4 f = p4[(size_t)j << 10];
            v[4 * j + 0] = f.x; v[4 * j + 1] = f.y;
            v[4 * j + 2] = f.z; v[4 * j + 3] = f.w;
        }
    }

    while (row < nrows) {
        const int nextrow = row + GRID;

        // ---- register prefetch: next row into vn (in flight during P1..P3)
        float vn[16];
        if (nextrow < nrows) {
            const float4* __restrict__ p4 =
                reinterpret_cast<const float4*>(in + (size_t)nextrow * N_ELEM + (t << 2));
#pragma unroll
            for (int j = 0; j < 4; j++) {
                float4 f = p4[(size_t)j << 10];
                vn[4 * j + 0] = f.x; vn[4 * j + 1] = f.y;
                vn[4 * j + 2] = f.z; vn[4 * j + 3] = f.w;
            }
        }

        // ---- P1: butterflies bits {13,12,1,0}; STS.128
        hadN<16>(v);
#pragma unroll
        for (int j = 0; j < 4; j++) {
            *reinterpret_cast<float4*>(&sh[pa + j * 4352]) =
                make_float4(v[4 * j + 0], v[4 * j + 1], v[4 * j + 2], v[4 * j + 3]);
        }
        __syncthreads();  // B1

        // ---- P2: bits {11..8}; in-place (same-address) writeback
#pragma unroll
        for (int r = 0; r < 16; r++) v[r] = sh[pb1 + r * 272];
        hadN<16>(v);
#pragma unroll
        for (int r = 0; r < 16; r++) sh[pb1 + r * 272] = v[r];
        __syncthreads();  // B2

        // ---- L2 prefetch of row+2 (zero regs; covers this thread's future
        //      LDG.128 addresses). DRAM is idlest in this window.
        {
            const int row2 = row + 2 * GRID;
            if (row2 < nrows) {
                const float* p = in + (size_t)row2 * N_ELEM + (t << 2);
#pragma unroll
                for (int j = 0; j < 4; j++) {
                    asm volatile("prefetch.global.L2 [%0];"
                                 :: "l"((const void*)(p + ((size_t)j << 12))));
                }
            }
        }

        // ---- P3: bits {7..4}
#pragma unroll
        for (int r = 0; r < 16; r++) v[r] = sh[pb2 + r * 16];
        __syncthreads();  // B3: smem free for next iteration's P1 writes
        hadN<16>(v);

        // ---- bits {3,2} on lane bits 3,2 via shfl-xor sign trick
#pragma unroll
        for (int r = 0; r < 16; r++) {
            float q = __shfl_xor_sync(0xffffffffu, v[r], 8);
            v[r] = fmaf(s3, v[r], q);
        }
#pragma unroll
        for (int r = 0; r < 16; r++) {
            float q = __shfl_xor_sync(0xffffffffu, v[r], 4);
            v[r] = fmaf(s2, v[r], q);
        }

        // ---- scale 2^-7, coalesced store (full 64B sectors)
        float* __restrict__ pout = out + (size_t)row * N_ELEM;
#pragma unroll
        for (int r = 0; r < 16; r++)
            pout[b2 + (r << 4)] = v[r] * 0.0078125f;

        // ---- rotate pipeline
        row = nextrow;
#pragma unroll
        for (int k = 0; k < 16; k++) v[k] = vn[k];
    }
}

extern "C" void kernel_launch(void* const* d_in, const int* in_sizes, int n_in,
                              void* d_out, int out_size) {
    const float* phi = (const float*)d_in[0];
    float* out = (float*)d_out;

    const size_t smem = SMEM_FLOATS * sizeof(float);  // 69632 B
    cudaFuncSetAttribute(fwht_kernel,
                         cudaFuncAttributeMaxDynamicSharedMemorySize,
                         (int)smem);

    const int nrows = in_sizes[0] / N_ELEM;  // 4096
    const int grid = nrows < GRID ? nrows : GRID;
    fwht_kernel<<<grid, THREADS, smem>>>(phi, out, nrows);
}